// round 8
// baseline (speedup 1.0000x reference)
#include <cuda_runtime.h>
#include <cstddef>

// CTC batch cost, prob-domain forward with exact power-of-two renormalization.
// One warp per batch element; lane l owns lattice states 4l..4l+3 (lane 31 also 128).
// Rows of y_pred are streamed coalesced into a 12-slot shared-memory ring via
// cp.async (prefetch distance 11 chunks = 44 KB in flight per warp); label
// gathers are LDS from the ring. B=512, T=512, C=128, L=64, S=129.

#define CTC_B 512
#define CTC_T 512
#define CTC_C 128
#define CTC_L 64
#define CHUNK 8                    // steps per chunk == renorm period
#define NCHUNK (CTC_T / CHUNK)     // 64
#define DIST 11                    // chunk-groups kept in flight
#define SLOTS 12                   // ring slots (DIST+1 decouples refill/consume)
#define DROWS (CHUNK * SLOTS)      // 96 ring rows = 48 KB (static smem limit)

__global__ __launch_bounds__(32)
void ctc_warp_kernel(const int* __restrict__ y_true,
                     const float* __restrict__ y_pred,
                     float* __restrict__ out)
{
    __shared__ float ring[DROWS * CTC_C];

    const int b    = blockIdx.x;
    const int lane = threadIdx.x;          // 0..31
    const unsigned FULL = 0xffffffffu;
    const float EPSF = 1e-7f;

    // Labels owned by this lane: k0 = 2*lane -> state 4l+1, k1 = 2*lane+1 -> state 4l+3
    const int c0 = y_true[b * CTC_L + 2 * lane];
    const int c1 = y_true[b * CTC_L + 2 * lane + 1];
    const int c1_prev = __shfl_up_sync(FULL, c1, 1);   // y[2l-1] lives in prev lane
    const bool skip1 = (lane > 0) && (c0 != c1_prev);  // state 4l+1: y[2l] != y[2l-1]
    const bool skip3 = (c1 != c0);                     // state 4l+3: y[2l+1] != y[2l]

    const float* row0 = y_pred + (size_t)b * CTC_T * CTC_C;

    // cp.async one full row (512B) coalesced: lane takes 16B at offset lane*16.
    const unsigned ring_base = (unsigned)__cvta_generic_to_shared(ring);
    auto load_chunk = [&](int c) {   // rows c*CHUNK.. into ring slot c%SLOTS
        const int sbase = (c % SLOTS) * CHUNK;
        if (c < NCHUNK) {
            #pragma unroll
            for (int j = 0; j < CHUNK; ++j) {
                const int t = c * CHUNK + j;
                unsigned dst = ring_base + (unsigned)(((sbase + j) * CTC_C + lane * 4) * 4);
                const float* src = row0 + (size_t)t * CTC_C + lane * 4;
                asm volatile("cp.async.cg.shared.global [%0], [%1], 16;\n"
                             :: "r"(dst), "l"(src));
            }
        }
        asm volatile("cp.async.commit_group;\n" ::: "memory");  // commit even if empty
    };

    // Prologue: DIST chunk-groups in flight.
    for (int c = 0; c < DIST; ++c) load_chunk(c);

    // Virtual alpha_{-1} = (2^100, 0, 0, ...) at lane 0; true alpha = stored * 2^K.
    const float TWO100 = __int_as_float((100 + 127) << 23);  // 2^100
    float a0 = (lane == 0) ? TWO100 : 0.0f;
    float a1 = 0.0f, a2 = 0.0f, a3 = 0.0f, a4 = 0.0f;
    float pm1 = 0.0f;     // alpha_{t-1}[4l-1] (prev lane's a3), pipelined shfl
    int   K   = -100;     // integer log2 of the accumulated scale

    for (int c = 0; c < NCHUNK; ++c) {
        // Issue group c+DIST first (writes the slot consumed at iteration c-1,
        // whose LDS reads completed a full iteration ago) — keeps DIST groups
        // in flight through the compute phase.
        load_chunk(c + DIST);

        // Group c must be complete; up to DIST newer groups stay pending.
        asm volatile("cp.async.wait_group %0;\n" :: "n"(DIST) : "memory");
        __syncwarp();   // cross-lane visibility of cp.async-written smem

        const int sbase = (c % SLOTS) * CHUNK;
        #pragma unroll
        for (int j = 0; j < CHUNK; ++j) {
            const float* rs = ring + (sbase + j) * CTC_C;
            const float pb = rs[CTC_C - 1] + EPSF;  // broadcast LDS
            const float p0 = rs[c0] + EPSF;         // scattered LDS
            const float p1 = rs[c1] + EPSF;

            // new[s] = p[s] * (a[s] + a[s-1] + skip*a[s-2]); states 4l..4l+3 (+128)
            const float n3 = p1 * ((a2 + (skip3 ? a1 : 0.0f)) + a3);   // s=4l+3 (label k1)
            const float n2 = pb * (a1 + a2);                           // s=4l+2 (blank)
            const float sh = __shfl_up_sync(FULL, n3, 1);              // next step's alpha[4l-1]
            const float n0 = pb * (a0 + pm1);                          // s=4l   (blank)
            const float n1 = p0 * ((a0 + (skip1 ? pm1 : 0.0f)) + a1);  // s=4l+1 (label k0)
            const float n4 = (lane == 31) ? pb * (a3 + a4) : 0.0f;     // s=128  (last blank)

            pm1 = (lane == 0) ? 0.0f : sh;
            a0 = n0; a1 = n1; a2 = n2; a3 = n3; a4 = n4;
        }

        // Exact renorm: warp max via redux (bits order-preserving for non-negative
        // floats), round down to 2^k, rescale so max sits in [2^100, 2^101).
        // Scale 2^(100-k) applied as two exact power-of-2 multiplies; K accumulates
        // the exact integer log2 of the total scale (zero rounding added).
        float m = fmaxf(fmaxf(fmaxf(a0, a1), fmaxf(a2, a3)), a4);
        m = __uint_as_float(__reduce_max_sync(FULL, __float_as_uint(m)));
        const int k = (int)((__float_as_uint(m) >> 23) & 0xff) - 127;  // floor(log2 m)
        K += k - 100;
        const float s1 = __int_as_float((127 - k) << 23);  // 2^-k   (exact)
        a0 = a0 * s1 * TWO100;
        a1 = a1 * s1 * TWO100;
        a2 = a2 * s1 * TWO100;
        a3 = a3 * s1 * TWO100;
        a4 = a4 * s1 * TWO100;
        pm1 = pm1 * s1 * TWO100;
    }

    // ll = log(alpha_T[S-2] + alpha_T[S-1]) + K*ln2 ; states 127,128 live in lane 31.
    if (lane == 31) {
        out[b] = -(logf(a3 + a4) + (float)K * 0.693147180559945309f);
    }
}

extern "C" void kernel_launch(void* const* d_in, const int* in_sizes, int n_in,
                              void* d_out, int out_size)
{
    // Resolve inputs by size (y_true: 512*64 int32, y_pred: 512*512*128 float32).
    const void* p0 = d_in[0];
    const void* p1 = d_in[1];
    const int* y_true;
    const float* y_pred;
    if (in_sizes[0] == CTC_B * CTC_L) {
        y_true = (const int*)p0;
        y_pred = (const float*)p1;
    } else {
        y_true = (const int*)p1;
        y_pred = (const float*)p0;
    }
    float* out = (float*)d_out;

    ctc_warp_kernel<<<CTC_B, 32>>>(y_true, y_pred, out);
}

// round 9
// speedup vs baseline: 1.1321x; 1.1321x over previous
#include <cuda_runtime.h>
#include <cstddef>

// CTC batch cost, prob-domain forward with exact power-of-two renormalization.
// Warp-specialized: per CTA, warp 0 = consumer (recurrence), warp 1 = producer
// (cp.async streaming), coupled by per-slot full/empty mbarriers. Full barriers
// complete via cp.async.mbarrier.arrive.noinc (32 lane completions); empty via
// a single lane-0 arrive after syncwarp. Ring: 8 slots x 8 rows = 32 KB.
// One CTA per batch element; consumer lane l owns lattice states 4l..4l+3
// (lane 31 also state 128). B=512, T=512, C=128, L=64, S=129.

#define CTC_B 512
#define CTC_T 512
#define CTC_C 128
#define CTC_L 64
#define CHUNK 8                     // steps per chunk == renorm period
#define NCHUNK (CTC_T / CHUNK)      // 64
#define SLOTS 8                     // ring slots (producer can run 8 chunks ahead)
#define CHUNK_BYTES (CHUNK * CTC_C * 4)   // 4096

__global__ __launch_bounds__(64)
void ctc_warp_kernel(const int* __restrict__ y_true,
                     const float* __restrict__ y_pred,
                     float* __restrict__ out)
{
    __shared__ __align__(128) float ring[SLOTS * CHUNK * CTC_C];   // 32 KB
    __shared__ __align__(8) unsigned long long mb_full[SLOTS];
    __shared__ __align__(8) unsigned long long mb_empty[SLOTS];

    const int b    = blockIdx.x;
    const int tid  = threadIdx.x;
    const int lane = tid & 31;
    const int wid  = tid >> 5;            // 0 = consumer, 1 = producer
    const unsigned FULL = 0xffffffffu;
    const float EPSF = 1e-7f;

    const float* row0 = y_pred + (size_t)b * CTC_T * CTC_C;
    const unsigned ring_base  = (unsigned)__cvta_generic_to_shared(ring);
    const unsigned full_base  = (unsigned)__cvta_generic_to_shared(mb_full);
    const unsigned empty_base = (unsigned)__cvta_generic_to_shared(mb_empty);

    if (tid == 0) {
        #pragma unroll
        for (int s = 0; s < SLOTS; ++s) {
            asm volatile("mbarrier.init.shared.b64 [%0], 32;"   // 32 cp.async completions
                         :: "r"(full_base + s * 8) : "memory");
            asm volatile("mbarrier.init.shared.b64 [%0], 1;"    // lane-0 release
                         :: "r"(empty_base + s * 8) : "memory");
        }
    }
    __syncthreads();

    // Parity wait: succeed once phase `par` of the barrier has completed.
    #define WAIT_PARITY(baraddr, par)                                              \
        asm volatile(                                                              \
            "{\n\t.reg .pred P;\n\t"                                               \
            "W_%=:\n\t"                                                           \
            "mbarrier.try_wait.parity.acquire.cta.shared::cta.b64 P, [%0], %1, 0x989680;\n\t" \
            "@!P bra W_%=;\n\t}"                                                  \
            :: "r"(baraddr), "r"(par) : "memory")

    if (wid == 1) {
        // ───────── Producer: free-running cp.async streamer ─────────
        int phase = 1;   // empty barriers start "available": first SLOTS waits pass
        for (int c = 0; c < NCHUNK; ++c) {
            const int slot = c % SLOTS;
            WAIT_PARITY(empty_base + slot * 8, (unsigned)phase);
            const unsigned dbase = ring_base + (unsigned)(slot * CHUNK_BYTES + lane * 16);
            const float* sbase = row0 + (size_t)c * CHUNK * CTC_C + lane * 4;
            #pragma unroll
            for (int j = 0; j < CHUNK; ++j) {
                asm volatile("cp.async.cg.shared.global [%0], [%1], 16;"
                             :: "r"(dbase + j * (CTC_C * 4)), "l"(sbase + j * CTC_C));
            }
            // Arrive on full[slot] when this lane's prior cp.asyncs complete.
            asm volatile("cp.async.mbarrier.arrive.noinc.shared.b64 [%0];"
                         :: "r"(full_base + slot * 8) : "memory");
            if (slot == SLOTS - 1) phase ^= 1;
        }
        return;   // producer exits; consumer never waits on it again
    }

    // ───────── Consumer: CTC recurrence ─────────
    // Labels owned by this lane: k0 = 2*lane -> state 4l+1, k1 = 2*lane+1 -> state 4l+3
    const int c0 = y_true[b * CTC_L + 2 * lane];
    const int c1 = y_true[b * CTC_L + 2 * lane + 1];
    const int c1_prev = __shfl_up_sync(FULL, c1, 1);   // y[2l-1] lives in prev lane
    const bool skip1 = (lane > 0) && (c0 != c1_prev);  // state 4l+1: y[2l] != y[2l-1]
    const bool skip3 = (c1 != c0);                     // state 4l+3: y[2l+1] != y[2l]

    // Virtual alpha_{-1} = (2^100, 0, 0, ...) at lane 0; true alpha = stored * 2^K.
    const float TWO100 = __int_as_float((100 + 127) << 23);  // 2^100
    float a0 = (lane == 0) ? TWO100 : 0.0f;
    float a1 = 0.0f, a2 = 0.0f, a3 = 0.0f, a4 = 0.0f;
    float pm1 = 0.0f;     // alpha_{t-1}[4l-1] (prev lane's a3), pipelined shfl
    int   K   = -100;     // integer log2 of the accumulated scale
    int   phase = 0;      // full barriers: wait for each slot's fill

    for (int c = 0; c < NCHUNK; ++c) {
        const int slot = c % SLOTS;
        WAIT_PARITY(full_base + slot * 8, (unsigned)phase);

        const float* rs0 = ring + slot * CHUNK * CTC_C;
        #pragma unroll
        for (int j = 0; j < CHUNK; ++j) {
            const float* rs = rs0 + j * CTC_C;
            const float pb = rs[CTC_C - 1] + EPSF;  // broadcast LDS
            const float p0 = rs[c0] + EPSF;         // scattered LDS
            const float p1 = rs[c1] + EPSF;

            // new[s] = p[s] * (a[s] + a[s-1] + skip*a[s-2]); states 4l..4l+3 (+128)
            const float n3 = p1 * ((a2 + (skip3 ? a1 : 0.0f)) + a3);   // s=4l+3 (label k1)
            const float n2 = pb * (a1 + a2);                           // s=4l+2 (blank)
            const float sh = __shfl_up_sync(FULL, n3, 1);              // next step's alpha[4l-1]
            const float n0 = pb * (a0 + pm1);                          // s=4l   (blank)
            const float n1 = p0 * ((a0 + (skip1 ? pm1 : 0.0f)) + a1);  // s=4l+1 (label k0)
            const float n4 = (lane == 31) ? pb * (a3 + a4) : 0.0f;     // s=128  (last blank)

            pm1 = (lane == 0) ? 0.0f : sh;
            a0 = n0; a1 = n1; a2 = n2; a3 = n3; a4 = n4;
        }

        // Release the slot (all lanes done reading), then renorm while the
        // producer refills it.
        __syncwarp();
        if (lane == 0) {
            asm volatile("mbarrier.arrive.shared.b64 _, [%0];"
                         :: "r"(empty_base + slot * 8) : "memory");
        }
        if (slot == SLOTS - 1) phase ^= 1;

        // Exact renorm: warp max via redux (bits order-preserving for non-negative
        // floats), round down to 2^k, rescale so max sits in [2^100, 2^101).
        // Scale 2^(100-k) applied as two exact power-of-2 multiplies; K accumulates
        // the exact integer log2 of the total scale (zero rounding added).
        float m = fmaxf(fmaxf(fmaxf(a0, a1), fmaxf(a2, a3)), a4);
        m = __uint_as_float(__reduce_max_sync(FULL, __float_as_uint(m)));
        const int k = (int)((__float_as_uint(m) >> 23) & 0xff) - 127;  // floor(log2 m)
        K += k - 100;
        const float s1 = __int_as_float((127 - k) << 23);  // 2^-k   (exact)
        a0 = a0 * s1 * TWO100;
        a1 = a1 * s1 * TWO100;
        a2 = a2 * s1 * TWO100;
        a3 = a3 * s1 * TWO100;
        a4 = a4 * s1 * TWO100;
        pm1 = pm1 * s1 * TWO100;
    }

    // ll = log(alpha_T[S-2] + alpha_T[S-1]) + K*ln2 ; states 127,128 live in lane 31.
    if (lane == 31) {
        out[b] = -(logf(a3 + a4) + (float)K * 0.693147180559945309f);
    }
    #undef WAIT_PARITY
}

extern "C" void kernel_launch(void* const* d_in, const int* in_sizes, int n_in,
                              void* d_out, int out_size)
{
    // Resolve inputs by size (y_true: 512*64 int32, y_pred: 512*512*128 float32).
    const void* p0 = d_in[0];
    const void* p1 = d_in[1];
    const int* y_true;
    const float* y_pred;
    if (in_sizes[0] == CTC_B * CTC_L) {
        y_true = (const int*)p0;
        y_pred = (const float*)p1;
    } else {
        y_true = (const int*)p1;
        y_pred = (const float*)p0;
    }
    float* out = (float*)d_out;

    ctc_warp_kernel<<<CTC_B, 64>>>(y_true, y_pred, out);
}